// round 1
// baseline (speedup 1.0000x reference)
#include <cuda_runtime.h>
#include <math.h>

#define NN 10000
#define DD 128
#define KK 16
#define SS 5
#define EE 320000
#define PP 80000
#define NSTEP 4
#define LN_EPS 1e-5f

// Scratch (no cudaMalloc allowed)
__device__ float g_seg[(size_t)NSTEP * NN * DD];   // [4][N][128]
__device__ float g_deg[NSTEP * NN];                // [4][N]

// ---------------------------------------------------------------------------
// Kernel 0: zero the scatter accumulators
// ---------------------------------------------------------------------------
__global__ void zero_kernel() {
    const int total_seg = NSTEP * NN * DD;
    const int total_deg = NSTEP * NN;
    int stride = gridDim.x * blockDim.x;
    for (int i = blockIdx.x * blockDim.x + threadIdx.x; i < total_seg; i += stride)
        g_seg[i] = 0.0f;
    for (int i = blockIdx.x * blockDim.x + threadIdx.x; i < total_deg; i += stride)
        g_deg[i] = 0.0f;
}

// ---------------------------------------------------------------------------
// Kernel 1: scatter-add messages. One warp per (step, perm-slot).
// msg = x[src] + rel_table[edge_type[e]]; atomically added into g_seg[s][dst].
// ---------------------------------------------------------------------------
__global__ __launch_bounds__(256) void scatter_kernel(
    const float* __restrict__ x,
    const int*   __restrict__ edge_index,
    const int*   __restrict__ edge_type,
    const int*   __restrict__ perms,
    const float* __restrict__ rel_table)
{
    int gw   = (blockIdx.x * blockDim.x + threadIdx.x) >> 5;   // global warp id
    int lane = threadIdx.x & 31;
    if (gw >= NSTEP * PP) return;

    int e   = perms[gw];                 // perms is [4][P] row-major; gw == s*P + p
    int s   = gw / PP;
    int src = edge_index[e];
    int dst = edge_index[EE + e];
    int rt  = edge_type[e];

    const float4* xs = (const float4*)(x + (size_t)src * DD);
    const float4* rs = (const float4*)(rel_table + (size_t)rt * DD);
    float* out = g_seg + ((size_t)s * NN + dst) * DD;

    float4 xv = xs[lane];
    float4 rv = rs[lane];
    int base = lane * 4;
    atomicAdd(out + base + 0, xv.x + rv.x);
    atomicAdd(out + base + 1, xv.y + rv.y);
    atomicAdd(out + base + 2, xv.z + rv.z);
    atomicAdd(out + base + 3, xv.w + rv.w);
    if (lane == 0) atomicAdd(&g_deg[s * NN + dst], 1.0f);
}

// ---------------------------------------------------------------------------
// Kernel 2: fused per-node GraphMamba layer. One 128-thread block per node.
// ---------------------------------------------------------------------------
__global__ __launch_bounds__(128) void node_kernel(
    const float* __restrict__ x,
    const float* __restrict__ log_A,
    const float* __restrict__ W_B,
    const float* __restrict__ W_C,
    const float* __restrict__ W_delta,
    const float* __restrict__ b_delta,
    const float* __restrict__ W_g,
    const float* __restrict__ b_g,
    const float* __restrict__ W_out,
    const float* __restrict__ b_out,
    const float* __restrict__ ln_g,
    const float* __restrict__ ln_b,
    float* __restrict__ out)
{
    __shared__ float tok[SS][DD];
    __shared__ float Bs[SS][KK];
    __shared__ float Cs[SS][KK];
    __shared__ float sc[DD];
    __shared__ float rbuf[4];

    const int n = blockIdx.x;
    const int d = threadIdx.x;

    // ---- build tokens -----------------------------------------------------
    tok[0][d] = x[(size_t)n * DD + d];
#pragma unroll
    for (int s = 1; s < SS; s++) {
        float dg  = g_deg[(s - 1) * NN + n];
        float inv = 1.0f / fmaxf(dg, 1.0f);
        tok[s][d] = g_seg[((size_t)(s - 1) * NN + n) * DD + d] * inv;
    }
    __syncthreads();

    // ---- deltas = softplus(tokens @ W_delta + b_delta) --------------------
    float del[SS];
    {
        float bd = b_delta[d];
#pragma unroll
        for (int s = 0; s < SS; s++) del[s] = bd;
    }
    for (int j = 0; j < DD; j += 4) {
        float w0 = W_delta[(j + 0) * DD + d];
        float w1 = W_delta[(j + 1) * DD + d];
        float w2 = W_delta[(j + 2) * DD + d];
        float w3 = W_delta[(j + 3) * DD + d];
#pragma unroll
        for (int s = 0; s < SS; s++) {
            float4 t = *(const float4*)&tok[s][j];
            del[s] += t.x * w0 + t.y * w1 + t.z * w2 + t.w * w3;
        }
    }
#pragma unroll
    for (int s = 0; s < SS; s++) {
        float v = del[s];
        del[s] = (v > 20.0f) ? v : log1pf(expf(v));
    }

    // ---- Bs, Cs = tokens @ W_B, tokens @ W_C ------------------------------
    if (d < SS * KK) {
        int s = d / KK, k = d % KK;
        float accB = 0.0f, accC = 0.0f;
        for (int j = 0; j < DD; j++) {
            float t = tok[s][j];
            accB += t * W_B[j * KK + k];
            accC += t * W_C[j * KK + k];
        }
        Bs[s][k] = accB;
        Cs[s][k] = accC;
    }
    __syncthreads();

    // ---- selective scan (fwd + bwd) ---------------------------------------
    float ac[KK];
#pragma unroll
    for (int k = 0; k < KK; k++)
        ac[k] = -__expf(log_A[d * KK + k]);

    float tokd[SS];
#pragma unroll
    for (int s = 0; s < SS; s++) tokd[s] = tok[s][d];

    float ysum = 0.0f;
    {   // forward
        float st[KK];
#pragma unroll
        for (int k = 0; k < KK; k++) st[k] = 0.0f;
#pragma unroll
        for (int s = 0; s < SS; s++) {
            float dl = del[s];
            float dx = dl * tokd[s];
            float y = 0.0f;
#pragma unroll
            for (int k = 0; k < KK; k++) {
                float a = __expf(dl * ac[k]);
                st[k] = a * st[k] + dx * Bs[s][k];
                y += st[k] * Cs[s][k];
            }
            ysum += y;
        }
    }
    {   // backward (reversed token order)
        float st[KK];
#pragma unroll
        for (int k = 0; k < KK; k++) st[k] = 0.0f;
#pragma unroll
        for (int si = 0; si < SS; si++) {
            int s = SS - 1 - si;
            float dl = del[s];
            float dx = dl * tokd[s];
            float y = 0.0f;
#pragma unroll
            for (int k = 0; k < KK; k++) {
                float a = __expf(dl * ac[k]);
                st[k] = a * st[k] + dx * Bs[s][k];
                y += st[k] * Cs[s][k];
            }
            ysum += y;
        }
    }
    sc[d] = ysum * (1.0f / SS);
    __syncthreads();

    // ---- gate + output projection ----------------------------------------
    float ga = b_g[d];
    float oa = b_out[d];
    for (int j = 0; j < DD; j += 4) {
        float4 t  = *(const float4*)&tok[0][j];
        float4 sv = *(const float4*)&sc[j];
        float g0 = W_g[(j + 0) * DD + d], o0 = W_out[(j + 0) * DD + d];
        float g1 = W_g[(j + 1) * DD + d], o1 = W_out[(j + 1) * DD + d];
        float g2 = W_g[(j + 2) * DD + d], o2 = W_out[(j + 2) * DD + d];
        float g3 = W_g[(j + 3) * DD + d], o3 = W_out[(j + 3) * DD + d];
        ga += t.x * g0 + t.y * g1 + t.z * g2 + t.w * g3;
        oa += sv.x * o0 + sv.y * o1 + sv.z * o2 + sv.w * o3;
    }
    float gate = ga / (1.0f + __expf(-ga));   // silu
    float res  = tokd[0] + gate * oa;

    // ---- LayerNorm (block reduce over 128) --------------------------------
    float v = res;
#pragma unroll
    for (int o = 16; o; o >>= 1) v += __shfl_xor_sync(0xffffffffu, v, o);
    if ((d & 31) == 0) rbuf[d >> 5] = v;
    __syncthreads();
    float mean = (rbuf[0] + rbuf[1] + rbuf[2] + rbuf[3]) * (1.0f / DD);
    __syncthreads();

    float c  = res - mean;
    float v2 = c * c;
#pragma unroll
    for (int o = 16; o; o >>= 1) v2 += __shfl_xor_sync(0xffffffffu, v2, o);
    if ((d & 31) == 0) rbuf[d >> 5] = v2;
    __syncthreads();
    float var = (rbuf[0] + rbuf[1] + rbuf[2] + rbuf[3]) * (1.0f / DD);

    out[(size_t)n * DD + d] = c * rsqrtf(var + LN_EPS) * ln_g[d] + ln_b[d];
}

// ---------------------------------------------------------------------------
extern "C" void kernel_launch(void* const* d_in, const int* in_sizes, int n_in,
                              void* d_out, int out_size)
{
    const float* x          = (const float*)d_in[0];
    const int*   edge_index = (const int*)  d_in[1];
    const int*   edge_type  = (const int*)  d_in[2];
    const int*   perms      = (const int*)  d_in[3];
    const float* rel_table  = (const float*)d_in[4];
    const float* log_A      = (const float*)d_in[5];
    const float* W_B        = (const float*)d_in[6];
    const float* W_C        = (const float*)d_in[7];
    const float* W_delta    = (const float*)d_in[8];
    const float* b_delta    = (const float*)d_in[9];
    const float* W_g        = (const float*)d_in[10];
    const float* b_g        = (const float*)d_in[11];
    const float* W_out      = (const float*)d_in[12];
    const float* b_out      = (const float*)d_in[13];
    const float* ln_g       = (const float*)d_in[14];
    const float* ln_b       = (const float*)d_in[15];
    float* out = (float*)d_out;

    zero_kernel<<<512, 256>>>();

    int total_warps = NSTEP * PP;                 // 320000
    int blocks = (total_warps * 32 + 255) / 256;  // 40000
    scatter_kernel<<<blocks, 256>>>(x, edge_index, edge_type, perms, rel_table);

    node_kernel<<<NN, 128>>>(x, log_A, W_B, W_C, W_delta, b_delta,
                             W_g, b_g, W_out, b_out, ln_g, ln_b, out);
}

// round 2
// speedup vs baseline: 1.2038x; 1.2038x over previous
#include <cuda_runtime.h>
#include <math.h>

#define NN 10000
#define DD 128
#define KK 16
#define SS 5
#define EE 320000
#define PP 80000
#define NSTEP 4
#define LN_EPS 1e-5f
#define NPB 4          // nodes per block in node_kernel
#define BT 192         // threads per block in node_kernel

// Scratch (no cudaMalloc allowed)
__device__ __align__(16) float g_seg[(size_t)NSTEP * NN * DD];   // [4][N][128]
__device__ float g_deg[NSTEP * NN];                              // [4][N]

// ---------------------------------------------------------------------------
// Kernel 0: zero the scatter accumulators (vectorized)
// ---------------------------------------------------------------------------
__global__ void zero_kernel() {
    const int total_seg4 = NSTEP * NN * DD / 4;
    const int total_deg = NSTEP * NN;
    int stride = gridDim.x * blockDim.x;
    float4 z = make_float4(0.f, 0.f, 0.f, 0.f);
    float4* seg4 = (float4*)g_seg;
    for (int i = blockIdx.x * blockDim.x + threadIdx.x; i < total_seg4; i += stride)
        seg4[i] = z;
    for (int i = blockIdx.x * blockDim.x + threadIdx.x; i < total_deg; i += stride)
        g_deg[i] = 0.0f;
}

// ---------------------------------------------------------------------------
// Kernel 1: scatter-add messages. One warp per (step, perm-slot).
// Uses red.global.add.v4.f32 => 1 L2 atomic op per 16B instead of 4.
// ---------------------------------------------------------------------------
__global__ __launch_bounds__(256) void scatter_kernel(
    const float* __restrict__ x,
    const int*   __restrict__ edge_index,
    const int*   __restrict__ edge_type,
    const int*   __restrict__ perms,
    const float* __restrict__ rel_table)
{
    int gw   = (blockIdx.x * blockDim.x + threadIdx.x) >> 5;   // global warp id
    int lane = threadIdx.x & 31;
    if (gw >= NSTEP * PP) return;

    int e   = perms[gw];                 // perms is [4][P] row-major; gw == s*P + p
    int s   = gw / PP;
    int src = edge_index[e];
    int dst = edge_index[EE + e];
    int rt  = edge_type[e];

    const float4* xs = (const float4*)(x + (size_t)src * DD);
    const float4* rs = (const float4*)(rel_table + (size_t)rt * DD);
    float* out = g_seg + ((size_t)s * NN + dst) * DD + lane * 4;

    float4 xv = xs[lane];
    float4 rv = rs[lane];
    float a0 = xv.x + rv.x;
    float a1 = xv.y + rv.y;
    float a2 = xv.z + rv.z;
    float a3 = xv.w + rv.w;

    asm volatile("red.global.add.v4.f32 [%0], {%1, %2, %3, %4};"
                 :: "l"(out), "f"(a0), "f"(a1), "f"(a2), "f"(a3)
                 : "memory");

    if (lane == 0) atomicAdd(&g_deg[s * NN + dst], 1.0f);
}

// ---------------------------------------------------------------------------
// Kernel 2: fused per-node GraphMamba layer. 192 threads, 4 nodes per block.
// Threads 0..127   -> delta-projection column d (and everything downstream)
// Threads 128..143 -> B-projection column k
// Threads 144..159 -> (unused pad)  -- actually B uses 16, C uses 16:
// Threads 128..143 -> B(k), 160..175 -> C(k)? We use contiguous: 128..143 B,
// 144..159 C, 160..191 idle during projection (kept for load/LN symmetry).
// ---------------------------------------------------------------------------
__global__ __launch_bounds__(BT) void node_kernel(
    const float* __restrict__ x,
    const float* __restrict__ log_A,
    const float* __restrict__ W_B,
    const float* __restrict__ W_C,
    const float* __restrict__ W_delta,
    const float* __restrict__ b_delta,
    const float* __restrict__ W_g,
    const float* __restrict__ b_g,
    const float* __restrict__ W_out,
    const float* __restrict__ b_out,
    const float* __restrict__ ln_g,
    const float* __restrict__ ln_b,
    float* __restrict__ out)
{
    __shared__ float tok[NPB][SS][DD];
    __shared__ float Bs[NPB][SS][KK];
    __shared__ float Cs[NPB][SS][KK];
    __shared__ float sc[NPB][DD];
    __shared__ float rbuf[NPB][4];

    const int n0 = blockIdx.x * NPB;
    const int t = threadIdx.x;

    // ---- build tokens (all 192 threads) -----------------------------------
    for (int idx = t; idx < NPB * SS * DD; idx += BT) {
        int m = idx / (SS * DD);
        int r = idx % (SS * DD);
        int s = r / DD;
        int d = r % DD;
        int n = n0 + m;
        float v;
        if (s == 0) {
            v = x[(size_t)n * DD + d];
        } else {
            float dg = g_deg[(s - 1) * NN + n];
            v = g_seg[((size_t)(s - 1) * NN + n) * DD + d] / fmaxf(dg, 1.0f);
        }
        tok[m][s][d] = v;
    }
    __syncthreads();

    // ---- fused projections: delta (128 cols) + B (16) + C (16) ------------
    float acc[NPB][SS];
    const float* wcol;
    int wstride;
    if (t < DD) {
        float bd = b_delta[t];
#pragma unroll
        for (int m = 0; m < NPB; m++)
#pragma unroll
            for (int s = 0; s < SS; s++) acc[m][s] = bd;
        wcol = W_delta + t;
        wstride = DD;
    } else {
#pragma unroll
        for (int m = 0; m < NPB; m++)
#pragma unroll
            for (int s = 0; s < SS; s++) acc[m][s] = 0.0f;
        if (t < DD + KK) { wcol = W_B + (t - DD); }
        else if (t < DD + 2 * KK) { wcol = W_C + (t - DD - KK); }
        else { wcol = W_B; }   // idle threads: harmless reads
        wstride = KK;
    }

    for (int j = 0; j < DD; j += 4) {
        float w0 = wcol[(j + 0) * wstride];
        float w1 = wcol[(j + 1) * wstride];
        float w2 = wcol[(j + 2) * wstride];
        float w3 = wcol[(j + 3) * wstride];
#pragma unroll
        for (int m = 0; m < NPB; m++)
#pragma unroll
            for (int s = 0; s < SS; s++) {
                float4 tv = *(const float4*)&tok[m][s][j];
                acc[m][s] += tv.x * w0 + tv.y * w1 + tv.z * w2 + tv.w * w3;
            }
    }

    if (t >= DD && t < DD + KK) {
        int k = t - DD;
#pragma unroll
        for (int m = 0; m < NPB; m++)
#pragma unroll
            for (int s = 0; s < SS; s++) Bs[m][s][k] = acc[m][s];
    } else if (t >= DD + KK && t < DD + 2 * KK) {
        int k = t - DD - KK;
#pragma unroll
        for (int m = 0; m < NPB; m++)
#pragma unroll
            for (int s = 0; s < SS; s++) Cs[m][s][k] = acc[m][s];
    } else if (t < DD) {
        // softplus on delta accumulators (keep in registers)
#pragma unroll
        for (int m = 0; m < NPB; m++)
#pragma unroll
            for (int s = 0; s < SS; s++) {
                float v = acc[m][s];
                acc[m][s] = (v > 20.0f) ? v : log1pf(expf(v));
            }
    }
    __syncthreads();

    // ---- selective scan (fwd + bwd), threads 0..127 ------------------------
    if (t < DD) {
        const int d = t;
        float ac[KK];
#pragma unroll
        for (int k = 0; k < KK; k++)
            ac[k] = -__expf(log_A[d * KK + k]);

#pragma unroll
        for (int m = 0; m < NPB; m++) {
            float tokd[SS];
#pragma unroll
            for (int s = 0; s < SS; s++) tokd[s] = tok[m][s][d];

            float ysum = 0.0f;
            {   // forward
                float st[KK];
#pragma unroll
                for (int k = 0; k < KK; k++) st[k] = 0.0f;
#pragma unroll
                for (int s = 0; s < SS; s++) {
                    float dl = acc[m][s];
                    float dx = dl * tokd[s];
#pragma unroll
                    for (int k = 0; k < KK; k++) {
                        float a = __expf(dl * ac[k]);
                        st[k] = a * st[k] + dx * Bs[m][s][k];
                        ysum += st[k] * Cs[m][s][k];
                    }
                }
            }
            {   // backward
                float st[KK];
#pragma unroll
                for (int k = 0; k < KK; k++) st[k] = 0.0f;
#pragma unroll
                for (int si = 0; si < SS; si++) {
                    int s = SS - 1 - si;
                    float dl = acc[m][s];
                    float dx = dl * tokd[s];
#pragma unroll
                    for (int k = 0; k < KK; k++) {
                        float a = __expf(dl * ac[k]);
                        st[k] = a * st[k] + dx * Bs[m][s][k];
                        ysum += st[k] * Cs[m][s][k];
                    }
                }
            }
            sc[m][d] = ysum * (1.0f / SS);
        }
    }
    __syncthreads();

    // ---- gate + output projection + LayerNorm ------------------------------
    float res[NPB];
#pragma unroll
    for (int m = 0; m < NPB; m++) res[m] = 0.0f;

    if (t < DD) {
        const int d = t;
        float ga[NPB], oa[NPB];
        float bg = b_g[d], bo = b_out[d];
#pragma unroll
        for (int m = 0; m < NPB; m++) { ga[m] = bg; oa[m] = bo; }

        for (int j = 0; j < DD; j += 4) {
            float g0 = W_g[(j + 0) * DD + d], o0 = W_out[(j + 0) * DD + d];
            float g1 = W_g[(j + 1) * DD + d], o1 = W_out[(j + 1) * DD + d];
            float g2 = W_g[(j + 2) * DD + d], o2 = W_out[(j + 2) * DD + d];
            float g3 = W_g[(j + 3) * DD + d], o3 = W_out[(j + 3) * DD + d];
#pragma unroll
            for (int m = 0; m < NPB; m++) {
                float4 tv = *(const float4*)&tok[m][0][j];
                float4 sv = *(const float4*)&sc[m][j];
                ga[m] += tv.x * g0 + tv.y * g1 + tv.z * g2 + tv.w * g3;
                oa[m] += sv.x * o0 + sv.y * o1 + sv.z * o2 + sv.w * o3;
            }
        }
#pragma unroll
        for (int m = 0; m < NPB; m++) {
            float gate = ga[m] / (1.0f + __expf(-ga[m]));   // silu
            res[m] = tok[m][0][d] + gate * oa[m];
        }
    }

    // LN mean: warps 0..3 hold the 128 d-values
    {
        float v[NPB];
#pragma unroll
        for (int m = 0; m < NPB; m++) v[m] = res[m];
#pragma unroll
        for (int o = 16; o; o >>= 1)
#pragma unroll
            for (int m = 0; m < NPB; m++)
                v[m] += __shfl_xor_sync(0xffffffffu, v[m], o);
        if (t < DD && (t & 31) == 0)
#pragma unroll
            for (int m = 0; m < NPB; m++) rbuf[m][t >> 5] = v[m];
    }
    __syncthreads();
    float mean[NPB];
#pragma unroll
    for (int m = 0; m < NPB; m++)
        mean[m] = (rbuf[m][0] + rbuf[m][1] + rbuf[m][2] + rbuf[m][3]) * (1.0f / DD);
    __syncthreads();

    {
        float v[NPB];
#pragma unroll
        for (int m = 0; m < NPB; m++) {
            float c = (t < DD) ? (res[m] - mean[m]) : 0.0f;
            v[m] = c * c;
        }
#pragma unroll
        for (int o = 16; o; o >>= 1)
#pragma unroll
            for (int m = 0; m < NPB; m++)
                v[m] += __shfl_xor_sync(0xffffffffu, v[m], o);
        if (t < DD && (t & 31) == 0)
#pragma unroll
            for (int m = 0; m < NPB; m++) rbuf[m][t >> 5] = v[m];
    }
    __syncthreads();

    if (t < DD) {
        const int d = t;
        float lg = ln_g[d], lb = ln_b[d];
#pragma unroll
        for (int m = 0; m < NPB; m++) {
            float var = (rbuf[m][0] + rbuf[m][1] + rbuf[m][2] + rbuf[m][3]) * (1.0f / DD);
            float c = res[m] - mean[m];
            out[(size_t)(n0 + m) * DD + d] = c * rsqrtf(var + LN_EPS) * lg + lb;
        }
    }
}

// ---------------------------------------------------------------------------
extern "C" void kernel_launch(void* const* d_in, const int* in_sizes, int n_in,
                              void* d_out, int out_size)
{
    const float* x          = (const float*)d_in[0];
    const int*   edge_index = (const int*)  d_in[1];
    const int*   edge_type  = (const int*)  d_in[2];
    const int*   perms      = (const int*)  d_in[3];
    const float* rel_table  = (const float*)d_in[4];
    const float* log_A      = (const float*)d_in[5];
    const float* W_B        = (const float*)d_in[6];
    const float* W_C        = (const float*)d_in[7];
    const float* W_delta    = (const float*)d_in[8];
    const float* b_delta    = (const float*)d_in[9];
    const float* W_g        = (const float*)d_in[10];
    const float* b_g        = (const float*)d_in[11];
    const float* W_out      = (const float*)d_in[12];
    const float* b_out      = (const float*)d_in[13];
    const float* ln_g       = (const float*)d_in[14];
    const float* ln_b       = (const float*)d_in[15];
    float* out = (float*)d_out;

    zero_kernel<<<512, 256>>>();

    int total_warps = NSTEP * PP;                 // 320000
    int blocks = (total_warps * 32 + 255) / 256;  // 40000
    scatter_kernel<<<blocks, 256>>>(x, edge_index, edge_type, perms, rel_table);

    node_kernel<<<NN / NPB, BT>>>(x, log_A, W_B, W_C, W_delta, b_delta,
                                  W_g, b_g, W_out, b_out, ln_g, ln_b, out);
}

// round 3
// speedup vs baseline: 1.3553x; 1.1258x over previous
#include <cuda_runtime.h>
#include <math.h>

#define NN 10000
#define DD 128
#define KK 16
#define SS 5
#define EE 320000
#define PP 80000
#define NSTEP 4
#define NSEG (NSTEP * NN)          // 40000 segments
#define NEDGE (NSTEP * PP)         // 320000 sampled edges
#define LN_EPS 1e-5f
#define NPB 4
#define BT 192

// Scratch (no cudaMalloc allowed)
__device__ __align__(16) float g_seg[(size_t)NSTEP * NN * DD];   // [4][N][128] (pre-divided neigh)
__device__ int  g_cnt[NSEG];
__device__ int  g_off[NSEG];
__device__ int  g_cur[NSEG];
__device__ __align__(8) int2 g_edges[NEDGE];                     // sorted (src, rel_type)

// ---------------------------------------------------------------------------
// Kernel 0: zero the histogram counters
// ---------------------------------------------------------------------------
__global__ void zero_cnt_kernel() {
    int i = blockIdx.x * blockDim.x + threadIdx.x;
    if (i < NSEG) g_cnt[i] = 0;
}

// ---------------------------------------------------------------------------
// Kernel 1: histogram of destinations per step
// ---------------------------------------------------------------------------
__global__ __launch_bounds__(256) void hist_kernel(
    const int* __restrict__ edge_index,
    const int* __restrict__ perms)
{
    int idx = blockIdx.x * blockDim.x + threadIdx.x;   // s*PP + p
    if (idx >= NEDGE) return;
    int e = perms[idx];
    int s = idx / PP;
    int dst = edge_index[EE + e];
    atomicAdd(&g_cnt[s * NN + dst], 1);
}

// ---------------------------------------------------------------------------
// Kernel 2: single-block exclusive prefix scan of g_cnt -> g_off, g_cur
// ---------------------------------------------------------------------------
__global__ __launch_bounds__(1024) void scan_kernel() {
    __shared__ int warp_sums[32];
    const int t = threadIdx.x;
    const int lane = t & 31;
    const int wid = t >> 5;
    int carry = 0;

    for (int base = 0; base < NSEG; base += 1024) {
        int i = base + t;
        int v = (i < NSEG) ? g_cnt[i] : 0;

        // inclusive warp scan
        int inc = v;
#pragma unroll
        for (int o = 1; o < 32; o <<= 1) {
            int nv = __shfl_up_sync(0xffffffffu, inc, o);
            if (lane >= o) inc += nv;
        }
        if (lane == 31) warp_sums[wid] = inc;
        __syncthreads();

        if (wid == 0) {
            int ws = warp_sums[lane];
#pragma unroll
            for (int o = 1; o < 32; o <<= 1) {
                int nv = __shfl_up_sync(0xffffffffu, ws, o);
                if (lane >= o) ws += nv;
            }
            warp_sums[lane] = ws;   // inclusive scan of warp sums
        }
        __syncthreads();

        int excl = inc - v + (wid > 0 ? warp_sums[wid - 1] : 0) + carry;
        if (i < NSEG) { g_off[i] = excl; g_cur[i] = excl; }
        carry += warp_sums[31];
        __syncthreads();
    }
}

// ---------------------------------------------------------------------------
// Kernel 3: placement — bucket edges by (step, dst), store (src, rel_type)
// ---------------------------------------------------------------------------
__global__ __launch_bounds__(256) void place_kernel(
    const int* __restrict__ edge_index,
    const int* __restrict__ edge_type,
    const int* __restrict__ perms)
{
    int idx = blockIdx.x * blockDim.x + threadIdx.x;
    if (idx >= NEDGE) return;
    int e = perms[idx];
    int s = idx / PP;
    int src = edge_index[e];
    int dst = edge_index[EE + e];
    int rt  = edge_type[e];
    int pos = atomicAdd(&g_cur[s * NN + dst], 1);
    g_edges[pos] = make_int2(src, rt);
}

// ---------------------------------------------------------------------------
// Kernel 4: gather — one warp per (step, node) segment, mean of messages
// ---------------------------------------------------------------------------
__global__ __launch_bounds__(256) void gather_kernel(
    const float* __restrict__ x,
    const float* __restrict__ rel_table)
{
    int seg  = (blockIdx.x * blockDim.x + threadIdx.x) >> 5;
    int lane = threadIdx.x & 31;
    if (seg >= NSEG) return;

    int off = g_off[seg];
    int cnt = g_cnt[seg];
    int end = off + cnt;

    const float4* x4 = (const float4*)x;
    const float4* r4 = (const float4*)rel_table;

    float4 acc = make_float4(0.f, 0.f, 0.f, 0.f);
    int i = off;
    for (; i + 1 < end; i += 2) {
        int2 e0 = g_edges[i];
        int2 e1 = g_edges[i + 1];
        float4 a0 = x4[(size_t)e0.x * 32 + lane];
        float4 b0 = r4[(size_t)e0.y * 32 + lane];
        float4 a1 = x4[(size_t)e1.x * 32 + lane];
        float4 b1 = r4[(size_t)e1.y * 32 + lane];
        acc.x += a0.x + b0.x + a1.x + b1.x;
        acc.y += a0.y + b0.y + a1.y + b1.y;
        acc.z += a0.z + b0.z + a1.z + b1.z;
        acc.w += a0.w + b0.w + a1.w + b1.w;
    }
    if (i < end) {
        int2 e0 = g_edges[i];
        float4 a0 = x4[(size_t)e0.x * 32 + lane];
        float4 b0 = r4[(size_t)e0.y * 32 + lane];
        acc.x += a0.x + b0.x;
        acc.y += a0.y + b0.y;
        acc.z += a0.z + b0.z;
        acc.w += a0.w + b0.w;
    }

    float inv = 1.0f / fmaxf((float)cnt, 1.0f);
    acc.x *= inv; acc.y *= inv; acc.z *= inv; acc.w *= inv;
    ((float4*)g_seg)[(size_t)seg * 32 + lane] = acc;
}

// ---------------------------------------------------------------------------
// Kernel 5: fused per-node GraphMamba layer. 192 threads, 4 nodes per block.
// ---------------------------------------------------------------------------
__global__ __launch_bounds__(BT) void node_kernel(
    const float* __restrict__ x,
    const float* __restrict__ log_A,
    const float* __restrict__ W_B,
    const float* __restrict__ W_C,
    const float* __restrict__ W_delta,
    const float* __restrict__ b_delta,
    const float* __restrict__ W_g,
    const float* __restrict__ b_g,
    const float* __restrict__ W_out,
    const float* __restrict__ b_out,
    const float* __restrict__ ln_g,
    const float* __restrict__ ln_b,
    float* __restrict__ out)
{
    __shared__ float tok[NPB][SS][DD];
    __shared__ float Bs[NPB][SS][KK];
    __shared__ float Cs[NPB][SS][KK];
    __shared__ float sc[NPB][DD];
    __shared__ float rbuf[NPB][4];

    const int n0 = blockIdx.x * NPB;
    const int t = threadIdx.x;

    // ---- build tokens (all 192 threads, vectorized) -----------------------
    // token layout: [m][s][d]; s=0 from x, s>0 from g_seg (pre-divided)
    for (int idx = t; idx < NPB * SS * DD / 4; idx += BT) {
        int m = idx / (SS * DD / 4);
        int r = idx % (SS * DD / 4);
        int s = r / (DD / 4);
        int q = r % (DD / 4);
        int n = n0 + m;
        float4 v;
        if (s == 0) v = ((const float4*)x)[(size_t)n * 32 + q];
        else        v = ((const float4*)g_seg)[((size_t)(s - 1) * NN + n) * 32 + q];
        *(float4*)&tok[m][s][q * 4] = v;
    }
    __syncthreads();

    // ---- fused projections: delta (128 cols) + B (16) + C (16) ------------
    float acc[NPB][SS];
    const float* wcol;
    int wstride;
    if (t < DD) {
        float bd = b_delta[t];
#pragma unroll
        for (int m = 0; m < NPB; m++)
#pragma unroll
            for (int s = 0; s < SS; s++) acc[m][s] = bd;
        wcol = W_delta + t;
        wstride = DD;
    } else {
#pragma unroll
        for (int m = 0; m < NPB; m++)
#pragma unroll
            for (int s = 0; s < SS; s++) acc[m][s] = 0.0f;
        if (t < DD + KK) { wcol = W_B + (t - DD); }
        else if (t < DD + 2 * KK) { wcol = W_C + (t - DD - KK); }
        else { wcol = W_B; }
        wstride = KK;
    }

    for (int j = 0; j < DD; j += 4) {
        float w0 = wcol[(j + 0) * wstride];
        float w1 = wcol[(j + 1) * wstride];
        float w2 = wcol[(j + 2) * wstride];
        float w3 = wcol[(j + 3) * wstride];
#pragma unroll
        for (int m = 0; m < NPB; m++)
#pragma unroll
            for (int s = 0; s < SS; s++) {
                float4 tv = *(const float4*)&tok[m][s][j];
                acc[m][s] += tv.x * w0 + tv.y * w1 + tv.z * w2 + tv.w * w3;
            }
    }

    if (t >= DD && t < DD + KK) {
        int k = t - DD;
#pragma unroll
        for (int m = 0; m < NPB; m++)
#pragma unroll
            for (int s = 0; s < SS; s++) Bs[m][s][k] = acc[m][s];
    } else if (t >= DD + KK && t < DD + 2 * KK) {
        int k = t - DD - KK;
#pragma unroll
        for (int m = 0; m < NPB; m++)
#pragma unroll
            for (int s = 0; s < SS; s++) Cs[m][s][k] = acc[m][s];
    } else if (t < DD) {
#pragma unroll
        for (int m = 0; m < NPB; m++)
#pragma unroll
            for (int s = 0; s < SS; s++) {
                float v = acc[m][s];
                acc[m][s] = (v > 20.0f) ? v : log1pf(expf(v));
            }
    }
    __syncthreads();

    // ---- selective scan (fwd + bwd), threads 0..127 ------------------------
    if (t < DD) {
        const int d = t;
        float ac[KK];
#pragma unroll
        for (int k = 0; k < KK; k++)
            ac[k] = -__expf(log_A[d * KK + k]);

#pragma unroll
        for (int m = 0; m < NPB; m++) {
            float tokd[SS];
#pragma unroll
            for (int s = 0; s < SS; s++) tokd[s] = tok[m][s][d];

            float ysum = 0.0f;
            {   // forward
                float st[KK];
#pragma unroll
                for (int k = 0; k < KK; k++) st[k] = 0.0f;
#pragma unroll
                for (int s = 0; s < SS; s++) {
                    float dl = acc[m][s];
                    float dx = dl * tokd[s];
#pragma unroll
                    for (int k = 0; k < KK; k++) {
                        float a = __expf(dl * ac[k]);
                        st[k] = a * st[k] + dx * Bs[m][s][k];
                        ysum += st[k] * Cs[m][s][k];
                    }
                }
            }
            {   // backward
                float st[KK];
#pragma unroll
                for (int k = 0; k < KK; k++) st[k] = 0.0f;
#pragma unroll
                for (int si = 0; si < SS; si++) {
                    int s = SS - 1 - si;
                    float dl = acc[m][s];
                    float dx = dl * tokd[s];
#pragma unroll
                    for (int k = 0; k < KK; k++) {
                        float a = __expf(dl * ac[k]);
                        st[k] = a * st[k] + dx * Bs[m][s][k];
                        ysum += st[k] * Cs[m][s][k];
                    }
                }
            }
            sc[m][d] = ysum * (1.0f / SS);
        }
    }
    __syncthreads();

    // ---- gate + output projection + LayerNorm ------------------------------
    float res[NPB];
#pragma unroll
    for (int m = 0; m < NPB; m++) res[m] = 0.0f;

    if (t < DD) {
        const int d = t;
        float ga[NPB], oa[NPB];
        float bg = b_g[d], bo = b_out[d];
#pragma unroll
        for (int m = 0; m < NPB; m++) { ga[m] = bg; oa[m] = bo; }

        for (int j = 0; j < DD; j += 4) {
            float g0 = W_g[(j + 0) * DD + d], o0 = W_out[(j + 0) * DD + d];
            float g1 = W_g[(j + 1) * DD + d], o1 = W_out[(j + 1) * DD + d];
            float g2 = W_g[(j + 2) * DD + d], o2 = W_out[(j + 2) * DD + d];
            float g3 = W_g[(j + 3) * DD + d], o3 = W_out[(j + 3) * DD + d];
#pragma unroll
            for (int m = 0; m < NPB; m++) {
                float4 tv = *(const float4*)&tok[m][0][j];
                float4 sv = *(const float4*)&sc[m][j];
                ga[m] += tv.x * g0 + tv.y * g1 + tv.z * g2 + tv.w * g3;
                oa[m] += sv.x * o0 + sv.y * o1 + sv.z * o2 + sv.w * o3;
            }
        }
#pragma unroll
        for (int m = 0; m < NPB; m++) {
            float gate = ga[m] / (1.0f + __expf(-ga[m]));   // silu
            res[m] = tok[m][0][d] + gate * oa[m];
        }
    }

    // LN mean
    {
        float v[NPB];
#pragma unroll
        for (int m = 0; m < NPB; m++) v[m] = res[m];
#pragma unroll
        for (int o = 16; o; o >>= 1)
#pragma unroll
            for (int m = 0; m < NPB; m++)
                v[m] += __shfl_xor_sync(0xffffffffu, v[m], o);
        if (t < DD && (t & 31) == 0)
#pragma unroll
            for (int m = 0; m < NPB; m++) rbuf[m][t >> 5] = v[m];
    }
    __syncthreads();
    float mean[NPB];
#pragma unroll
    for (int m = 0; m < NPB; m++)
        mean[m] = (rbuf[m][0] + rbuf[m][1] + rbuf[m][2] + rbuf[m][3]) * (1.0f / DD);
    __syncthreads();

    // LN var
    {
        float v[NPB];
#pragma unroll
        for (int m = 0; m < NPB; m++) {
            float c = (t < DD) ? (res[m] - mean[m]) : 0.0f;
            v[m] = c * c;
        }
#pragma unroll
        for (int o = 16; o; o >>= 1)
#pragma unroll
            for (int m = 0; m < NPB; m++)
                v[m] += __shfl_xor_sync(0xffffffffu, v[m], o);
        if (t < DD && (t & 31) == 0)
#pragma unroll
            for (int m = 0; m < NPB; m++) rbuf[m][t >> 5] = v[m];
    }
    __syncthreads();

    if (t < DD) {
        const int d = t;
        float lg = ln_g[d], lb = ln_b[d];
#pragma unroll
        for (int m = 0; m < NPB; m++) {
            float var = (rbuf[m][0] + rbuf[m][1] + rbuf[m][2] + rbuf[m][3]) * (1.0f / DD);
            float c = res[m] - mean[m];
            out[(size_t)(n0 + m) * DD + d] = c * rsqrtf(var + LN_EPS) * lg + lb;
        }
    }
}

// ---------------------------------------------------------------------------
extern "C" void kernel_launch(void* const* d_in, const int* in_sizes, int n_in,
                              void* d_out, int out_size)
{
    const float* x          = (const float*)d_in[0];
    const int*   edge_index = (const int*)  d_in[1];
    const int*   edge_type  = (const int*)  d_in[2];
    const int*   perms      = (const int*)  d_in[3];
    const float* rel_table  = (const float*)d_in[4];
    const float* log_A      = (const float*)d_in[5];
    const float* W_B        = (const float*)d_in[6];
    const float* W_C        = (const float*)d_in[7];
    const float* W_delta    = (const float*)d_in[8];
    const float* b_delta    = (const float*)d_in[9];
    const float* W_g        = (const float*)d_in[10];
    const float* b_g        = (const float*)d_in[11];
    const float* W_out      = (const float*)d_in[12];
    const float* b_out      = (const float*)d_in[13];
    const float* ln_g       = (const float*)d_in[14];
    const float* ln_b       = (const float*)d_in[15];
    float* out = (float*)d_out;

    zero_cnt_kernel<<<(NSEG + 255) / 256, 256>>>();
    hist_kernel<<<(NEDGE + 255) / 256, 256>>>(edge_index, perms);
    scan_kernel<<<1, 1024>>>();
    place_kernel<<<(NEDGE + 255) / 256, 256>>>(edge_index, edge_type, perms);
    gather_kernel<<<(NSEG * 32 + 255) / 256, 256>>>(x, rel_table);
    node_kernel<<<NN / NPB, BT>>>(x, log_A, W_B, W_C, W_delta, b_delta,
                                  W_g, b_g, W_out, b_out, ln_g, ln_b, out);
}

// round 4
// speedup vs baseline: 2.5214x; 1.8605x over previous
#include <cuda_runtime.h>
#include <math.h>

#define NN 10000
#define DD 128
#define KK 16
#define SS 5
#define EE 320000
#define PP 80000
#define NSTEP 4
#define NSEG (NSTEP * NN)
#define NEDGE (NSTEP * PP)
#define LN_EPS 1e-5f
#define NPB 4
#define BT 128

typedef unsigned long long ull;

__device__ __forceinline__ ull fma2(ull a, ull b, ull c) {
    ull d; asm("fma.rn.f32x2 %0, %1, %2, %3;" : "=l"(d) : "l"(a), "l"(b), "l"(c));
    return d;
}
__device__ __forceinline__ ull pack2(float lo, float hi) {
    ull r; asm("mov.b64 %0, {%1,%2};" : "=l"(r) : "f"(lo), "f"(hi)); return r;
}
__device__ __forceinline__ void unpack2(ull v, float& lo, float& hi) {
    asm("mov.b64 {%0,%1}, %2;" : "=f"(lo), "=f"(hi) : "l"(v));
}

// Scratch (no cudaMalloc allowed)
__device__ __align__(16) float g_seg[(size_t)NSTEP * NN * DD];
__device__ int  g_cnt[NSEG];
__device__ int  g_off[NSEG];
__device__ int  g_cur[NSEG];
__device__ __align__(8) int2 g_edges[NEDGE];

// ---------------------------------------------------------------------------
__global__ void zero_cnt_kernel() {
    int i = blockIdx.x * blockDim.x + threadIdx.x;
    if (i < NSEG) g_cnt[i] = 0;
}

__global__ __launch_bounds__(256) void hist_kernel(
    const int* __restrict__ edge_index, const int* __restrict__ perms)
{
    int idx = blockIdx.x * blockDim.x + threadIdx.x;
    if (idx >= NEDGE) return;
    int e = perms[idx];
    int s = idx / PP;
    atomicAdd(&g_cnt[s * NN + edge_index[EE + e]], 1);
}

__global__ __launch_bounds__(1024) void scan_kernel() {
    __shared__ int warp_sums[32];
    const int t = threadIdx.x, lane = t & 31, wid = t >> 5;
    int carry = 0;
    for (int base = 0; base < NSEG; base += 1024) {
        int i = base + t;
        int v = (i < NSEG) ? g_cnt[i] : 0;
        int inc = v;
#pragma unroll
        for (int o = 1; o < 32; o <<= 1) {
            int nv = __shfl_up_sync(0xffffffffu, inc, o);
            if (lane >= o) inc += nv;
        }
        if (lane == 31) warp_sums[wid] = inc;
        __syncthreads();
        if (wid == 0) {
            int ws = warp_sums[lane];
#pragma unroll
            for (int o = 1; o < 32; o <<= 1) {
                int nv = __shfl_up_sync(0xffffffffu, ws, o);
                if (lane >= o) ws += nv;
            }
            warp_sums[lane] = ws;
        }
        __syncthreads();
        int excl = inc - v + (wid > 0 ? warp_sums[wid - 1] : 0) + carry;
        if (i < NSEG) { g_off[i] = excl; g_cur[i] = excl; }
        carry += warp_sums[31];
        __syncthreads();
    }
}

__global__ __launch_bounds__(256) void place_kernel(
    const int* __restrict__ edge_index, const int* __restrict__ edge_type,
    const int* __restrict__ perms)
{
    int idx = blockIdx.x * blockDim.x + threadIdx.x;
    if (idx >= NEDGE) return;
    int e = perms[idx];
    int s = idx / PP;
    int pos = atomicAdd(&g_cur[s * NN + edge_index[EE + e]], 1);
    g_edges[pos] = make_int2(edge_index[e], edge_type[e]);
}

__global__ __launch_bounds__(256) void gather_kernel(
    const float* __restrict__ x, const float* __restrict__ rel_table)
{
    int seg  = (blockIdx.x * blockDim.x + threadIdx.x) >> 5;
    int lane = threadIdx.x & 31;
    if (seg >= NSEG) return;
    int off = g_off[seg], cnt = g_cnt[seg], end = off + cnt;
    const float4* x4 = (const float4*)x;
    const float4* r4 = (const float4*)rel_table;
    float4 acc = make_float4(0.f, 0.f, 0.f, 0.f);
    int i = off;
    for (; i + 1 < end; i += 2) {
        int2 e0 = g_edges[i];
        int2 e1 = g_edges[i + 1];
        float4 a0 = x4[(size_t)e0.x * 32 + lane];
        float4 b0 = r4[(size_t)e0.y * 32 + lane];
        float4 a1 = x4[(size_t)e1.x * 32 + lane];
        float4 b1 = r4[(size_t)e1.y * 32 + lane];
        acc.x += a0.x + b0.x + a1.x + b1.x;
        acc.y += a0.y + b0.y + a1.y + b1.y;
        acc.z += a0.z + b0.z + a1.z + b1.z;
        acc.w += a0.w + b0.w + a1.w + b1.w;
    }
    if (i < end) {
        int2 e0 = g_edges[i];
        float4 a0 = x4[(size_t)e0.x * 32 + lane];
        float4 b0 = r4[(size_t)e0.y * 32 + lane];
        acc.x += a0.x + b0.x; acc.y += a0.y + b0.y;
        acc.z += a0.z + b0.z; acc.w += a0.w + b0.w;
    }
    float inv = 1.0f / fmaxf((float)cnt, 1.0f);
    acc.x *= inv; acc.y *= inv; acc.z *= inv; acc.w *= inv;
    ((float4*)g_seg)[(size_t)seg * 32 + lane] = acc;
}

// ---------------------------------------------------------------------------
// Fused per-node layer. 128 threads, 4 nodes/block, f32x2-packed projections,
// single-pass bidirectional scan (shared exp).
// ---------------------------------------------------------------------------
__global__ __launch_bounds__(BT, 4) void node_kernel(
    const float* __restrict__ x,
    const float* __restrict__ log_A,
    const float* __restrict__ W_B,
    const float* __restrict__ W_C,
    const float* __restrict__ W_delta,
    const float* __restrict__ b_delta,
    const float* __restrict__ W_g,
    const float* __restrict__ b_g,
    const float* __restrict__ W_out,
    const float* __restrict__ b_out,
    const float* __restrict__ ln_g,
    const float* __restrict__ ln_b,
    float* __restrict__ out)
{
    __shared__ __align__(16) float tokp[SS][DD][NPB];   // node-minor tokens
    __shared__ float Bs[NPB][SS][KK];
    __shared__ float Cs[NPB][SS][KK];
    __shared__ __align__(16) float scp[DD][NPB];
    __shared__ float rbuf[NPB][4];

    const int n0 = blockIdx.x * NPB;
    const int t = threadIdx.x;          // = column d

    // ---- build tokens (node-minor layout) ---------------------------------
#pragma unroll
    for (int m = 0; m < NPB; m++) {
        int n = n0 + m;
        tokp[0][t][m] = x[(size_t)n * DD + t];
#pragma unroll
        for (int s = 1; s < SS; s++)
            tokp[s][t][m] = g_seg[((size_t)(s - 1) * NN + n) * DD + t];
    }
    __syncthreads();

    // ---- delta projection, f32x2-packed over node pairs -------------------
    ull accp[2][SS];
    {
        float bd = b_delta[t];
        ull bd2 = pack2(bd, bd);
#pragma unroll
        for (int s = 0; s < SS; s++) { accp[0][s] = bd2; accp[1][s] = bd2; }
    }
#pragma unroll 4
    for (int j = 0; j < DD; j++) {
        float w = W_delta[j * DD + t];
        ull w2 = pack2(w, w);
#pragma unroll
        for (int s = 0; s < SS; s++) {
            ulonglong2 tv = *(const ulonglong2*)&tokp[s][j][0];  // broadcast
            accp[0][s] = fma2(tv.x, w2, accp[0][s]);
            accp[1][s] = fma2(tv.y, w2, accp[1][s]);
        }
    }
    float del[NPB][SS];
#pragma unroll
    for (int s = 0; s < SS; s++) {
        unpack2(accp[0][s], del[0][s], del[1][s]);
        unpack2(accp[1][s], del[2][s], del[3][s]);
    }
#pragma unroll
    for (int m = 0; m < NPB; m++)
#pragma unroll
        for (int s = 0; s < SS; s++) {
            float v = del[m][s];
            del[m][s] = (v > 20.0f) ? v : log1pf(__expf(v));
        }

    // ---- B/C projections: 160 cooperative tasks ---------------------------
    for (int task = t; task < 2 * SS * KK; task += BT) {
        int which = task / (SS * KK);
        int r = task % (SS * KK);
        int s = r / KK, k = r % KK;
        const float* W = which ? W_C : W_B;
        float am0 = 0.f, am1 = 0.f, am2 = 0.f, am3 = 0.f;
        for (int j = 0; j < DD; j++) {
            float w = W[j * KK + k];
            float4 tv = *(const float4*)&tokp[s][j][0];
            am0 += tv.x * w; am1 += tv.y * w; am2 += tv.z * w; am3 += tv.w * w;
        }
        float* dst = which ? &Cs[0][s][k] : &Bs[0][s][k];
        dst[0 * SS * KK] = am0; dst[1 * SS * KK] = am1;
        dst[2 * SS * KK] = am2; dst[3 * SS * KK] = am3;
    }
    __syncthreads();

    // ---- single-pass bidirectional selective scan -------------------------
    const int d = t;
    float ac[KK];
    {
        const float4* la = (const float4*)(log_A + d * KK);
#pragma unroll
        for (int q = 0; q < KK / 4; q++) {
            float4 v = la[q];
            ac[q * 4 + 0] = -__expf(v.x);
            ac[q * 4 + 1] = -__expf(v.y);
            ac[q * 4 + 2] = -__expf(v.z);
            ac[q * 4 + 3] = -__expf(v.w);
        }
    }

#pragma unroll
    for (int m = 0; m < NPB; m++) {
        float F[KK], Dv[KK], ap[KK];
#pragma unroll
        for (int k = 0; k < KK; k++) { F[k] = 0.f; Dv[k] = 0.f; ap[k] = 0.f; }
        float ys = 0.f, yb = 0.f;
#pragma unroll
        for (int s = 0; s < SS; s++) {
            float dl = del[m][s];
            float dx = dl * tokp[s][d][m];
#pragma unroll
            for (int k = 0; k < KK; k++) {
                float a  = __expf(dl * ac[k]);
                float bx = dx * Bs[m][s][k];
                float C  = Cs[m][s][k];
                F[k]  = fmaf(a, F[k], bx);          // fwd state
                ys    = fmaf(C, F[k], ys);
                Dv[k] = fmaf(ap[k], Dv[k], C);      // bwd accumulator
                yb    = fmaf(bx, Dv[k], yb);
                ap[k] = a;
            }
        }
        scp[d][m] = (ys + yb) * (1.0f / SS);
    }
    __syncthreads();

    // ---- gate + out projection, f32x2-packed ------------------------------
    ull ga01, ga23, oa01, oa23;
    {
        float bg = b_g[d], bo = b_out[d];
        ga01 = ga23 = pack2(bg, bg);
        oa01 = oa23 = pack2(bo, bo);
    }
#pragma unroll 4
    for (int j = 0; j < DD; j++) {
        float g = W_g[j * DD + d];
        float o = W_out[j * DD + d];
        ull g2 = pack2(g, g), o2 = pack2(o, o);
        ulonglong2 tv = *(const ulonglong2*)&tokp[0][j][0];
        ulonglong2 sv = *(const ulonglong2*)&scp[j][0];
        ga01 = fma2(tv.x, g2, ga01);
        ga23 = fma2(tv.y, g2, ga23);
        oa01 = fma2(sv.x, o2, oa01);
        oa23 = fma2(sv.y, o2, oa23);
    }
    float res[NPB];
    {
        float ga[NPB], oa[NPB];
        unpack2(ga01, ga[0], ga[1]); unpack2(ga23, ga[2], ga[3]);
        unpack2(oa01, oa[0], oa[1]); unpack2(oa23, oa[2], oa[3]);
#pragma unroll
        for (int m = 0; m < NPB; m++) {
            float gate = ga[m] / (1.0f + __expf(-ga[m]));
            res[m] = tokp[0][d][m] + gate * oa[m];
        }
    }

    // ---- LayerNorm --------------------------------------------------------
    {
        float v[NPB];
#pragma unroll
        for (int m = 0; m < NPB; m++) v[m] = res[m];
#pragma unroll
        for (int o = 16; o; o >>= 1)
#pragma unroll
            for (int m = 0; m < NPB; m++)
                v[m] += __shfl_xor_sync(0xffffffffu, v[m], o);
        if ((t & 31) == 0)
#pragma unroll
            for (int m = 0; m < NPB; m++) rbuf[m][t >> 5] = v[m];
    }
    __syncthreads();
    float mean[NPB];
#pragma unroll
    for (int m = 0; m < NPB; m++)
        mean[m] = (rbuf[m][0] + rbuf[m][1] + rbuf[m][2] + rbuf[m][3]) * (1.0f / DD);
    __syncthreads();
    {
        float v[NPB];
#pragma unroll
        for (int m = 0; m < NPB; m++) {
            float c = res[m] - mean[m];
            v[m] = c * c;
        }
#pragma unroll
        for (int o = 16; o; o >>= 1)
#pragma unroll
            for (int m = 0; m < NPB; m++)
                v[m] += __shfl_xor_sync(0xffffffffu, v[m], o);
        if ((t & 31) == 0)
#pragma unroll
            for (int m = 0; m < NPB; m++) rbuf[m][t >> 5] = v[m];
    }
    __syncthreads();
    {
        float lg = ln_g[d], lb = ln_b[d];
#pragma unroll
        for (int m = 0; m < NPB; m++) {
            float var = (rbuf[m][0] + rbuf[m][1] + rbuf[m][2] + rbuf[m][3]) * (1.0f / DD);
            float c = res[m] - mean[m];
            out[(size_t)(n0 + m) * DD + d] = c * rsqrtf(var + LN_EPS) * lg + lb;
        }
    }
}

// ---------------------------------------------------------------------------
extern "C" void kernel_launch(void* const* d_in, const int* in_sizes, int n_in,
                              void* d_out, int out_size)
{
    const float* x          = (const float*)d_in[0];
    const int*   edge_index = (const int*)  d_in[1];
    const int*   edge_type  = (const int*)  d_in[2];
    const int*   perms      = (const int*)  d_in[3];
    const float* rel_table  = (const float*)d_in[4];
    const float* log_A      = (const float*)d_in[5];
    const float* W_B        = (const float*)d_in[6];
    const float* W_C        = (const float*)d_in[7];
    const float* W_delta    = (const float*)d_in[8];
    const float* b_delta    = (const float*)d_in[9];
    const float* W_g        = (const float*)d_in[10];
    const float* b_g        = (const float*)d_in[11];
    const float* W_out      = (const float*)d_in[12];
    const float* b_out      = (const float*)d_in[13];
    const float* ln_g       = (const float*)d_in[14];
    const float* ln_b       = (const float*)d_in[15];
    float* out = (float*)d_out;

    zero_cnt_kernel<<<(NSEG + 255) / 256, 256>>>();
    hist_kernel<<<(NEDGE + 255) / 256, 256>>>(edge_index, perms);
    scan_kernel<<<1, 1024>>>();
    place_kernel<<<(NEDGE + 255) / 256, 256>>>(edge_index, edge_type, perms);
    gather_kernel<<<(NSEG * 32 + 255) / 256, 256>>>(x, rel_table);
    node_kernel<<<NN / NPB, BT>>>(x, log_A, W_B, W_C, W_delta, b_delta,
                                  W_g, b_g, W_out, b_out, ln_g, ln_b, out);
}